// round 12
// baseline (speedup 1.0000x reference)
#include <cuda_runtime.h>
#include <cuda_fp16.h>
#include <cstdint>
#include <math.h>

// ============================================================================
// DUQ head via HMMA 3xFP16-split GEMM with FUSED feature split (register-only).
// out[b,c,p] = exp(-3.125 * sum_e (emb[p, c*16+e] - cent[c*16+e])^2)
// emb = feat[b,:,p].w[n,:], n=c*16+e, K=512.
// a = ah+al, b = bh+bl (exact fp16 splits); acc += ah*bh + ah*bl + al*bh (f32).
// A path: cp.async raw fp32 feature tile [k 0..31][px 0..127] (rows padded to
// 528B -> all fragment LDS.32 are bank-conflict-free), each thread loads its
// 8 A-fragment values directly and splits to hi/lo fp16 in registers.
// No prep_feat kernel, no half-A smem image, no extra syncs vs R9.
// B path: prepped (prep_w) + ldmatrix, identical to R9.
// CTA tile 128x128, warp tile 32x64 (8 warps/256 thr), BK=32,
// 3-stage cp.async, ~100KB smem, 2 CTAs/SM.
// ============================================================================

#define BM 128
#define BN 128
#define BK 32
#define KTILES 16
#define A_PITCH 528                 // 512B data + 16B pad (132 words, %32 = 4)
#define OFF_B   16896               // 32 * 528
#define OFF_BLO 8192                // within B region
#define STAGE_BYTES 33280           // rawA 16896 + B 16384
#define CENT_OFF (3 * STAGE_BYTES)  // 99840
#define SMEM_TOTAL (CENT_OFF + 512)

// -------- device-global scratch (no cudaMalloc allowed) ----------------------
__device__ __half g_bh[524288];     // [1024 n][512 k], n = c*16+e
__device__ __half g_bl[524288];
__device__ float  g_cent[1024];

// -------- helpers -------------------------------------------------------------
__device__ __forceinline__ uint32_t smem_u32(const void* p) {
    uint32_t a;
    asm("{ .reg .u64 t; cvta.to.shared.u64 t, %1; cvt.u32.u64 %0, t; }" : "=r"(a) : "l"(p));
    return a;
}
__device__ __forceinline__ void cp16h(uint32_t dst, const __half* src) {
    asm volatile("cp.async.cg.shared.global [%0], [%1], 16;"
                 :: "r"(dst), "l"(__cvta_generic_to_global(src)));
}
__device__ __forceinline__ void cp16f(uint32_t dst, const float* src) {
    asm volatile("cp.async.cg.shared.global [%0], [%1], 16;"
                 :: "r"(dst), "l"(__cvta_generic_to_global(src)));
}
__device__ __forceinline__ void ldsm4(uint32_t* r, uint32_t addr) {
    asm volatile("ldmatrix.sync.aligned.m8n8.x4.shared.b16 {%0,%1,%2,%3}, [%4];"
                 : "=r"(r[0]), "=r"(r[1]), "=r"(r[2]), "=r"(r[3]) : "r"(addr));
}
__device__ __forceinline__ float ldsf(uint32_t addr) {
    float v;
    asm volatile("ld.shared.f32 %0, [%1];" : "=f"(v) : "r"(addr));
    return v;
}
__device__ __forceinline__ void mma_f32(float* c, const uint32_t* a, const uint32_t* b) {
    asm volatile("mma.sync.aligned.m16n8k16.row.col.f32.f16.f16.f32 "
                 "{%0,%1,%2,%3}, {%4,%5,%6,%7}, {%8,%9}, {%0,%1,%2,%3};"
                 : "+f"(c[0]), "+f"(c[1]), "+f"(c[2]), "+f"(c[3])
                 : "r"(a[0]), "r"(a[1]), "r"(a[2]), "r"(a[3]), "r"(b[0]), "r"(b[1]));
}
// split a float pair into packed fp16 hi and lo (exact residual)
__device__ __forceinline__ void split2(float f0, float f1, uint32_t& hi, uint32_t& lo) {
    __half2 h = __floats2half2_rn(f0, f1);
    float2 b = __half22float2(h);
    __half2 l2 = __floats2half2_rn(f0 - b.x, f1 - b.y);
    hi = *(uint32_t*)&h;
    lo = *(uint32_t*)&l2;
}

// -------- prep: weights reorder + split, centroids ----------------------------
__global__ void prep_w(const float* __restrict__ wgt, const float* __restrict__ m,
                       const float* __restrict__ Nb) {
    int n = blockIdx.x;                 // n = c*16 + e
    int c = n >> 4, e = n & 15;
    const float* src = wgt + ((size_t)e * 64 + c) * 512;
    for (int k = threadIdx.x; k < 512; k += 128) {
        float v = src[k];
        __half hi = __float2half_rn(v);
        g_bh[(size_t)n * 512 + k] = hi;
        g_bl[(size_t)n * 512 + k] = __float2half_rn(v - __half2float(hi));
    }
    if (threadIdx.x == 0) g_cent[n] = m[e * 64 + c] / Nb[c];
}

// -------- stage fill (256 threads): A raw 4 cp + B 4 cp per thread -------------
__device__ __forceinline__ void fill_stage(uint32_t sb, int s, int kt, const float* feat,
                                           int bb, int pinbase, int n0, int t) {
    int kb = kt * BK;
    uint32_t st = sb + s * STAGE_BYTES;
    // raw A: [k][px] fp32, 32 rows x 512B, pitch 528B
    {
        int k = t >> 3, cb4 = (t & 7) * 4;
        const float* src = feat + ((size_t)(bb * 512 + kb + k)) * 16384 + pinbase + cb4 * 4;
        uint32_t d = st + (uint32_t)(k * A_PITCH + cb4 * 16);
#pragma unroll
        for (int jj = 0; jj < 4; jj++)
            cp16f(d + jj * 16, src + jj * 4);
    }
    // B: [n][k] halves, 64B rows, swizzle chunk ^ ((n>>1)&3)
    {
        int r = t >> 2, cB = t & 3;
#pragma unroll
        for (int i = 0; i < 2; i++) {
            int rr = r + i * 64;
            uint32_t d = st + OFF_B + (uint32_t)(rr * 64 + ((cB ^ ((rr >> 1) & 3)) << 4));
            size_t bsrc = (size_t)(n0 + rr) * 512 + kb + cB * 8;
            cp16h(d,           g_bh + bsrc);
            cp16h(d + OFF_BLO, g_bl + bsrc);
        }
    }
}

// -------- main GEMM + fused RBF epilogue ---------------------------------------
__global__ __launch_bounds__(256, 2) void duq_mma(const float* __restrict__ feat,
                                                  float* __restrict__ out) {
    extern __shared__ char smem[];
    uint32_t sb = smem_u32(smem);
    int t = threadIdx.x, l = t & 31, w = t >> 5;
    int nb = blockIdx.x, mb = blockIdx.y;
    long P0 = (long)mb * BM;           // 128 | 16384 -> never crosses a batch
    int bb = (int)(P0 >> 14);
    int pinbase = (int)(P0 & 16383);
    int n0 = nb * BN;

    if (t < BN) ((float*)(smem + CENT_OFF))[t] = g_cent[n0 + t];

    int wm = (w >> 1) * 32;            // 4 M-groups of 32
    int wn = (w & 1) * 64;             // 2 N-groups of 64

    int rl  = l & 7;                   // for B ldsm addressing
    int mh  = (l >> 3) & 1;
    int hi  = (l >> 4) & 1;
    int r4  = l >> 2;                  // 0..7  A fragment row
    int c2  = (l & 3) * 2;             // 0,2,4,6  A fragment col base (k)

    float acc[2][8][4];
#pragma unroll
    for (int i = 0; i < 2; i++)
#pragma unroll
        for (int j = 0; j < 8; j++)
#pragma unroll
            for (int q = 0; q < 4; q++) acc[i][j][q] = 0.0f;

    fill_stage(sb, 0, 0, feat, bb, pinbase, n0, t);
    asm volatile("cp.async.commit_group;" ::: "memory");
    fill_stage(sb, 1, 1, feat, bb, pinbase, n0, t);
    asm volatile("cp.async.commit_group;" ::: "memory");

    for (int kt = 0; kt < KTILES; kt++) {
        asm volatile("cp.async.wait_group 1;" ::: "memory");
        __syncthreads();

        if (kt + 2 < KTILES) fill_stage(sb, (kt + 2) % 3, kt + 2, feat, bb, pinbase, n0, t);
        asm volatile("cp.async.commit_group;" ::: "memory");

        uint32_t As = sb + (kt % 3) * STAGE_BYTES;
        uint32_t Bs = As + OFF_B;
#pragma unroll
        for (int k16 = 0; k16 < 2; k16++) {
            // ---- A fragments: direct LDS.32 from raw fp32 + register split ----
            // value f(px, k) at As + k*528 + px*4 ; thread owns
            // reg0=(r,c|c+1) reg1=(r+8,..) reg2=(r,c+8|c+9) reg3=(r+8,c+8|c+9)
            uint32_t ah[2][4], al[2][4];
            uint32_t abase = As + (uint32_t)((k16 * 16 + c2) * A_PITCH + (wm + r4) * 4);
#pragma unroll
            for (int mf = 0; mf < 2; mf++) {
                uint32_t ab = abase + mf * 64;
                float f0, f1;
                f0 = ldsf(ab);                         f1 = ldsf(ab + A_PITCH);
                split2(f0, f1, ah[mf][0], al[mf][0]);
                f0 = ldsf(ab + 32);                    f1 = ldsf(ab + A_PITCH + 32);
                split2(f0, f1, ah[mf][1], al[mf][1]);
                f0 = ldsf(ab + 8 * A_PITCH);           f1 = ldsf(ab + 9 * A_PITCH);
                split2(f0, f1, ah[mf][2], al[mf][2]);
                f0 = ldsf(ab + 8 * A_PITCH + 32);      f1 = ldsf(ab + 9 * A_PITCH + 32);
                split2(f0, f1, ah[mf][3], al[mf][3]);
            }
            // ---- B fragments via ldsm + 3-product MMAs (R9 form) ----
#pragma unroll
            for (int np = 0; np < 4; np++) {
                int rb = wn + np * 16 + hi * 8 + rl;
                uint32_t off = (uint32_t)(rb * 64 + (((2 * k16 + mh) ^ ((rb >> 1) & 3)) << 4));
                uint32_t bh4[4], bl4[4];
                ldsm4(bh4, Bs + off);
                ldsm4(bl4, Bs + OFF_BLO + off);
#pragma unroll
                for (int mf = 0; mf < 2; mf++)
#pragma unroll
                    for (int h = 0; h < 2; h++)
                        mma_f32(acc[mf][2 * np + h], ah[mf], &bh4[2 * h]);
#pragma unroll
                for (int mf = 0; mf < 2; mf++)
#pragma unroll
                    for (int h = 0; h < 2; h++)
                        mma_f32(acc[mf][2 * np + h], ah[mf], &bl4[2 * h]);
#pragma unroll
                for (int mf = 0; mf < 2; mf++)
#pragma unroll
                    for (int h = 0; h < 2; h++)
                        mma_f32(acc[mf][2 * np + h], al[mf], &bh4[2 * h]);
            }
        }
    }

    // ---- epilogue: diff^2, 16-e reduction (2 quad shuffles), __expf, store ----
    const float* centS = (const float*)(smem + CENT_OFF);
    int q2 = l & 3;
    int cb = (n0 + wn) >> 4;

#pragma unroll
    for (int mf = 0; mf < 2; mf++) {
        float s[4][2];
#pragma unroll
        for (int ch = 0; ch < 4; ch++) { s[ch][0] = 0.0f; s[ch][1] = 0.0f; }
#pragma unroll
        for (int nf = 0; nf < 8; nf++) {
            int ch = nf >> 1;
#pragma unroll
            for (int j = 0; j < 2; j++) {
                float ce = centS[wn + nf * 8 + 2 * q2 + j];
                float d0 = acc[mf][nf][j]     - ce;
                float d1 = acc[mf][nf][2 + j] - ce;
                s[ch][0] = fmaf(d0, d0, s[ch][0]);
                s[ch][1] = fmaf(d1, d1, s[ch][1]);
            }
        }
#pragma unroll
        for (int ch = 0; ch < 4; ch++)
#pragma unroll
            for (int r = 0; r < 2; r++) {
                s[ch][r] += __shfl_xor_sync(0xFFFFFFFFu, s[ch][r], 1);
                s[ch][r] += __shfl_xor_sync(0xFFFFFFFFu, s[ch][r], 2);
            }
        float v0 = (q2 == 0) ? s[0][0] : (q2 == 1) ? s[1][0] : (q2 == 2) ? s[2][0] : s[3][0];
        float v1 = (q2 == 0) ? s[0][1] : (q2 == 1) ? s[1][1] : (q2 == 2) ? s[2][1] : s[3][1];

        long gp = P0 + wm + mf * 16 + (l >> 2);
        int b   = (int)(gp >> 14);
        int pin = (int)(gp & 16383);
        int ch  = cb + q2;
        float* o = out + ((size_t)b * 64 + ch) * 16384 + pin;
        o[0] = __expf(-3.125f * v0);
        o[8] = __expf(-3.125f * v1);
    }
}

// -------- launch ----------------------------------------------------------------
extern "C" void kernel_launch(void* const* d_in, const int* in_sizes, int n_in,
                              void* d_out, int out_size)
{
    const float* feat = (const float*)d_in[0];   // [8, 512, 128, 128]
    const float* wgt  = (const float*)d_in[1];   // [16, 64, 512]
    const float* m    = (const float*)d_in[2];   // [16, 64]
    const float* N    = (const float*)d_in[3];   // [64]
    float* out        = (float*)d_out;           // [8, 64, 128, 128]

    cudaFuncSetAttribute(duq_mma, cudaFuncAttributeMaxDynamicSharedMemorySize, SMEM_TOTAL);

    prep_w<<<1024, 128>>>(wgt, m, N);
    duq_mma<<<dim3(8, 1024), 256, SMEM_TOTAL>>>(feat, out);
}

// round 13
// speedup vs baseline: 1.2943x; 1.2943x over previous
#include <cuda_runtime.h>
#include <cuda_fp16.h>
#include <cstdint>
#include <math.h>

// ============================================================================
// DUQ head via HMMA 3xFP16-split GEMM (R9 pipeline) + transpose-free prep.
// out[b,c,p] = exp(-3.125 * sum_e (emb[p, c*16+e] - cent[c*16+e])^2)
// emb = feat[b,:,p].w[n,:], n=c*16+e, K=512.
// a = ah+al, b = bh+bl (exact fp16 splits); acc += ah*bh + ah*bl + al*bh (f32).
// Feature halves stored in the SAME [b,k,p] layout as the input (elementwise
// streaming split, no transpose); A tiles are k-major in smem and A fragments
// are loaded with ldmatrix.x4.trans (addressing proven correct in R10).
// CTA tile 128x128, warp tile 32x64 (8 warps/256 thr), BK=32,
// 3-stage cp.async, 96KB smem, 2 CTAs/SM.
// ============================================================================

#define BM 128
#define BN 128
#define BK 32
#define KTILES 16            // 512 / 32
#define STAGE_BYTES 32768    // Ahi 8K | Alo 8K | Bhi 8K | Blo 8K
#define OFF_ALO 8192
#define OFF_BHI 16384
#define OFF_BLO 24576
#define CENT_OFF (3 * STAGE_BYTES)
#define SMEM_TOTAL (CENT_OFF + 512)

// -------- device-global scratch (no cudaMalloc allowed) ----------------------
__device__ __half g_ah[67108864];   // [8 b][512 k][16384 p]  (same layout as feat)
__device__ __half g_al[67108864];
__device__ __half g_bh[524288];     // [1024 n][512 k], n = c*16+e
__device__ __half g_bl[524288];
__device__ float  g_cent[1024];

// -------- helpers -------------------------------------------------------------
__device__ __forceinline__ uint32_t smem_u32(const void* p) {
    uint32_t a;
    asm("{ .reg .u64 t; cvta.to.shared.u64 t, %1; cvt.u32.u64 %0, t; }" : "=r"(a) : "l"(p));
    return a;
}
__device__ __forceinline__ void cp16(uint32_t dst, const __half* src) {
    asm volatile("cp.async.cg.shared.global [%0], [%1], 16;"
                 :: "r"(dst), "l"(__cvta_generic_to_global(src)));
}
__device__ __forceinline__ void ldsm4(uint32_t* r, uint32_t addr) {
    asm volatile("ldmatrix.sync.aligned.m8n8.x4.shared.b16 {%0,%1,%2,%3}, [%4];"
                 : "=r"(r[0]), "=r"(r[1]), "=r"(r[2]), "=r"(r[3]) : "r"(addr));
}
__device__ __forceinline__ void ldsm4t(uint32_t* r, uint32_t addr) {
    asm volatile("ldmatrix.sync.aligned.m8n8.x4.trans.shared.b16 {%0,%1,%2,%3}, [%4];"
                 : "=r"(r[0]), "=r"(r[1]), "=r"(r[2]), "=r"(r[3]) : "r"(addr));
}
__device__ __forceinline__ void mma_f32(float* c, const uint32_t* a, const uint32_t* b) {
    asm volatile("mma.sync.aligned.m16n8k16.row.col.f32.f16.f16.f32 "
                 "{%0,%1,%2,%3}, {%4,%5,%6,%7}, {%8,%9}, {%0,%1,%2,%3};"
                 : "+f"(c[0]), "+f"(c[1]), "+f"(c[2]), "+f"(c[3])
                 : "r"(a[0]), "r"(a[1]), "r"(a[2]), "r"(a[3]), "r"(b[0]), "r"(b[1]));
}

// -------- prep 1: elementwise fp16 split, NO transpose (streaming) ------------
__global__ void prep_feat(const float4* __restrict__ feat4) {
    size_t i = (size_t)blockIdx.x * 256 + threadIdx.x;   // float4 index
    float4 v = __ldcs(feat4 + i);
    __half2 h0 = __floats2half2_rn(v.x, v.y);
    __half2 h1 = __floats2half2_rn(v.z, v.w);
    float2 f0 = __half22float2(h0);
    float2 f1 = __half22float2(h1);
    __half2 l0 = __floats2half2_rn(v.x - f0.x, v.y - f0.y);
    __half2 l1 = __floats2half2_rn(v.z - f1.x, v.w - f1.y);
    uint2 hi2 = make_uint2(*(uint32_t*)&h0, *(uint32_t*)&h1);
    uint2 lo2 = make_uint2(*(uint32_t*)&l0, *(uint32_t*)&l1);
    __stcs(((uint2*)g_ah) + i, hi2);
    __stcs(((uint2*)g_al) + i, lo2);
}

// -------- prep 2: weights reorder + split, centroids --------------------------
__global__ void prep_w(const float* __restrict__ wgt, const float* __restrict__ m,
                       const float* __restrict__ Nb) {
    int n = blockIdx.x;                 // n = c*16 + e
    int c = n >> 4, e = n & 15;
    const float* src = wgt + ((size_t)e * 64 + c) * 512;
    for (int k = threadIdx.x; k < 512; k += 128) {
        float v = src[k];
        __half hi = __float2half_rn(v);
        g_bh[(size_t)n * 512 + k] = hi;
        g_bl[(size_t)n * 512 + k] = __float2half_rn(v - __half2float(hi));
    }
    if (threadIdx.x == 0) g_cent[n] = m[e * 64 + c] / Nb[c];
}

// -------- stage fill (256 threads): 8 x 16B cp.async per thread ----------------
// A: k-major, 32 rows x 256B (128 px), chunk swizzle c ^ (k&7)
// B: n-major, 128 rows x 64B, chunk swizzle c ^ ((n>>1)&3)
__device__ __forceinline__ void fill_stage(uint32_t sb, int s, int kt,
                                           int bb, int pinbase, int n0, int t) {
    int kb = kt * BK;
    uint32_t st = sb + s * STAGE_BYTES;
    {
        int k = t >> 3, c0 = (t & 7) * 2;
        size_t src = ((size_t)(bb * 512 + kb + k)) * 16384 + pinbase;
        uint32_t row = st + (uint32_t)(k * 256);
#pragma unroll
        for (int j = 0; j < 2; j++) {
            int c = c0 + j;
            uint32_t d = row + (uint32_t)((c ^ (k & 7)) << 4);
            cp16(d,           g_ah + src + c * 8);
            cp16(d + OFF_ALO, g_al + src + c * 8);
        }
    }
    {
        int r = t >> 2, cB = t & 3;
#pragma unroll
        for (int i = 0; i < 2; i++) {
            int rr = r + i * 64;
            uint32_t d = st + OFF_BHI + (uint32_t)(rr * 64 + ((cB ^ ((rr >> 1) & 3)) << 4));
            size_t bsrc = (size_t)(n0 + rr) * 512 + kb + cB * 8;
            cp16(d,                       g_bh + bsrc);
            cp16(d + (OFF_BLO - OFF_BHI), g_bl + bsrc);
        }
    }
}

// -------- main GEMM + fused RBF epilogue ---------------------------------------
__global__ __launch_bounds__(256, 2) void duq_mma(float* __restrict__ out) {
    extern __shared__ char smem[];
    uint32_t sb = smem_u32(smem);
    int t = threadIdx.x, l = t & 31, w = t >> 5;
    int nb = blockIdx.x, mb = blockIdx.y;
    long P0 = (long)mb * BM;           // 128 | 16384 -> never crosses a batch
    int bb = (int)(P0 >> 14);
    int pinbase = (int)(P0 & 16383);
    int n0 = nb * BN;

    if (t < BN) ((float*)(smem + CENT_OFF))[t] = g_cent[n0 + t];

    int wm = (w >> 1) * 32;            // 4 M-groups of 32
    int wn = (w & 1) * 64;             // 2 N-groups of 64

    int rl  = l & 7;                   // row within 8-row matrix
    int mh  = (l >> 3) & 1;            // matrix half bit
    int hi  = (l >> 4) & 1;            // k-chunk bit

    float acc[2][8][4];
#pragma unroll
    for (int i = 0; i < 2; i++)
#pragma unroll
        for (int j = 0; j < 8; j++)
#pragma unroll
            for (int q = 0; q < 4; q++) acc[i][j][q] = 0.0f;

    fill_stage(sb, 0, 0, bb, pinbase, n0, t);
    asm volatile("cp.async.commit_group;" ::: "memory");
    fill_stage(sb, 1, 1, bb, pinbase, n0, t);
    asm volatile("cp.async.commit_group;" ::: "memory");

    for (int kt = 0; kt < KTILES; kt++) {
        asm volatile("cp.async.wait_group 1;" ::: "memory");
        __syncthreads();

        if (kt + 2 < KTILES) fill_stage(sb, (kt + 2) % 3, kt + 2, bb, pinbase, n0, t);
        asm volatile("cp.async.commit_group;" ::: "memory");

        uint32_t As = sb + (kt % 3) * STAGE_BYTES;
#pragma unroll
        for (int k16 = 0; k16 < 2; k16++) {
            // A fragments from k-major halves via ldmatrix.trans (R10-proven)
            uint32_t ah[2][4], al[2][4];
            int krow = k16 * 16 + hi * 8 + rl;
#pragma unroll
            for (int mf = 0; mf < 2; mf++) {
                int pcol = wm + mf * 16 + mh * 8;
                uint32_t ad = As + (uint32_t)(krow * 256 + (((pcol >> 3) ^ rl) << 4));
                ldsm4t(ah[mf], ad);
                ldsm4t(al[mf], ad + OFF_ALO);
            }
#pragma unroll
            for (int np = 0; np < 4; np++) {
                int rb = wn + np * 16 + hi * 8 + rl;
                uint32_t off = (uint32_t)(rb * 64 + (((2 * k16 + mh) ^ ((rb >> 1) & 3)) << 4));
                uint32_t bh4[4], bl4[4];
                ldsm4(bh4, As + OFF_BHI + off);
                ldsm4(bl4, As + OFF_BLO + off);
#pragma unroll
                for (int mf = 0; mf < 2; mf++)
#pragma unroll
                    for (int h = 0; h < 2; h++)
                        mma_f32(acc[mf][2 * np + h], ah[mf], &bh4[2 * h]);
#pragma unroll
                for (int mf = 0; mf < 2; mf++)
#pragma unroll
                    for (int h = 0; h < 2; h++)
                        mma_f32(acc[mf][2 * np + h], ah[mf], &bl4[2 * h]);
#pragma unroll
                for (int mf = 0; mf < 2; mf++)
#pragma unroll
                    for (int h = 0; h < 2; h++)
                        mma_f32(acc[mf][2 * np + h], al[mf], &bh4[2 * h]);
            }
        }
    }

    // ---- epilogue: diff^2, 16-e reduction (2 quad shuffles), __expf, store ----
    const float* centS = (const float*)(smem + CENT_OFF);
    int q2 = l & 3;
    int cb = (n0 + wn) >> 4;           // first of this warp's 4 channels

#pragma unroll
    for (int mf = 0; mf < 2; mf++) {
        float s[4][2];
#pragma unroll
        for (int ch = 0; ch < 4; ch++) { s[ch][0] = 0.0f; s[ch][1] = 0.0f; }
#pragma unroll
        for (int nf = 0; nf < 8; nf++) {
            int ch = nf >> 1;
#pragma unroll
            for (int j = 0; j < 2; j++) {
                float ce = centS[wn + nf * 8 + 2 * q2 + j];
                float d0 = acc[mf][nf][j]     - ce;
                float d1 = acc[mf][nf][2 + j] - ce;
                s[ch][0] = fmaf(d0, d0, s[ch][0]);
                s[ch][1] = fmaf(d1, d1, s[ch][1]);
            }
        }
#pragma unroll
        for (int ch = 0; ch < 4; ch++)
#pragma unroll
            for (int r = 0; r < 2; r++) {
                s[ch][r] += __shfl_xor_sync(0xFFFFFFFFu, s[ch][r], 1);
                s[ch][r] += __shfl_xor_sync(0xFFFFFFFFu, s[ch][r], 2);
            }
        float v0 = (q2 == 0) ? s[0][0] : (q2 == 1) ? s[1][0] : (q2 == 2) ? s[2][0] : s[3][0];
        float v1 = (q2 == 0) ? s[0][1] : (q2 == 1) ? s[1][1] : (q2 == 2) ? s[2][1] : s[3][1];

        long gp = P0 + wm + mf * 16 + (l >> 2);
        int b   = (int)(gp >> 14);
        int pin = (int)(gp & 16383);
        int ch  = cb + q2;
        float* o = out + ((size_t)b * 64 + ch) * 16384 + pin;
        o[0] = __expf(-3.125f * v0);
        o[8] = __expf(-3.125f * v1);
    }
}

// -------- launch ----------------------------------------------------------------
extern "C" void kernel_launch(void* const* d_in, const int* in_sizes, int n_in,
                              void* d_out, int out_size)
{
    const float* feat = (const float*)d_in[0];   // [8, 512, 128, 128]
    const float* wgt  = (const float*)d_in[1];   // [16, 64, 512]
    const float* m    = (const float*)d_in[2];   // [16, 64]
    const float* N    = (const float*)d_in[3];   // [64]
    float* out        = (float*)d_out;           // [8, 64, 128, 128]

    cudaFuncSetAttribute(duq_mma, cudaFuncAttributeMaxDynamicSharedMemorySize, SMEM_TOTAL);

    prep_feat<<<65536, 256>>>((const float4*)feat);
    prep_w<<<1024, 128>>>(wgt, m, N);
    duq_mma<<<dim3(8, 1024), 256, SMEM_TOTAL>>>(out);
}